// round 14
// baseline (speedup 1.0000x reference)
#include <cuda_runtime.h>
#include <cuda_bf16.h>

#define NN 512
#define TT 32
#define MMSG 31
#define EE 64
#define AA 64
#define NREL 201
#define NTOK (NN*TT)
#define PB 64
#define CAP 1024
#define CHUNKS 8
#define SELF_BIN (256 + 200)
#define NCTA 444   // 3 CTAs per SM (148*3) — all co-resident, barrier-safe

// ---- device scratch ---------------------------------------------------------
__device__ float g_self[NN * EE];
__device__ float g_q[NTOK * AA];
__device__ float g_k[NTOK * AA];
__device__ float g_v[NTOK * AA];
__device__ int   g_cur[2 * 256];          // zero at load; re-zeroed each run
__device__ int   g_list[2 * 256 * CAP];
__device__ unsigned g_barcnt = 0;
__device__ unsigned g_bargen = 0;

// ---- grid-wide barrier (all NCTA CTAs resident) -------------------------------
__device__ __forceinline__ void grid_sync() {
    __syncthreads();
    if (threadIdx.x == 0) {
        __threadfence();
        unsigned gen = atomicAdd(&g_bargen, 0u);
        if (atomicAdd(&g_barcnt, 1u) == NCTA - 1u) {
            atomicExch(&g_barcnt, 0u);
            atomicAdd(&g_bargen, 1u);
        } else {
            while (atomicAdd(&g_bargen, 0u) == gen) {}
        }
    }
    __syncthreads();
}

// ---- shared memory union (max phase = proj: 48 KB) ----------------------------
struct __align__(16) ProjS  { float Ws1[EE*AA]; float Ws2[EE*AA]; float xb[EE][PB]; };
struct __align__(16) PrepS  { float Ws[EE*EE]; float hb[8][EE]; };
#define KHALF 16
#define QST 68
#define KTST 18
struct __align__(16) AttnS {
    float qs[TT * QST];
    float vs[KHALF * QST];
    float kT[EE * KTST];
    float sc[TT][KHALF + 1];
    float att0[KHALF];
    float pooled[AA];
};
union __align__(16) SmemU { ProjS p; PrepS s; AttnS a; };

__global__ __launch_bounds__(256) void k_fused(const float* __restrict__ h,
                                               const float* __restrict__ msg,
                                               const int* __restrict__ mt,
                                               const int* __restrict__ rln,
                                               const int* __restrict__ rlm,
                                               const float* __restrict__ W_self,
                                               const float* __restrict__ Q,
                                               const float* __restrict__ K,
                                               const float* __restrict__ V,
                                               const float* __restrict__ ffn_w,
                                               const float* __restrict__ ffn_b,
                                               float* __restrict__ out) {
    __shared__ SmemU smu;
    const int bid = blockIdx.x, tid = threadIdx.x;

    // ================= PHASE 1: scatter (0..63) + self GEMM (64..127) ========
    if (bid < 64) {
        if (tid < 128)
            ((float4*)out)[bid * 128 + tid] = make_float4(0.f, 0.f, 0.f, 0.f);
        const int t = bid * 256 + tid;
        const int n = t >> 5, m = t & 31;
        if (m == 0) {
            const int rqv = rln[n];
            int p0 = atomicAdd(&g_cur[rqv], 1);
            g_list[rqv * CAP + p0] = t;
            g_list[SELF_BIN * CAP + n] = t;   // deterministic slot, no atomic
        } else {
            const int i = n * MMSG + m - 1;
            const int rqv = rlm[i], rk = mt[i];
            int p0 = atomicAdd(&g_cur[rqv], 1);
            g_list[rqv * CAP + p0] = t;
            int p1 = atomicAdd(&g_cur[256 + rk], 1);
            g_list[(256 + rk) * CAP + p1] = t;
        }
        if (bid == 0 && tid == 0) g_cur[SELF_BIN] = NN;
    } else if (bid < 128) {
        float* Ws = smu.s.Ws;
        float (*hb)[EE] = smu.s.hb;
        const int n0 = (bid - 64) * 8;
        for (int i = tid; i < EE * EE / 4; i += 256)
            ((float4*)Ws)[i] = ((const float4*)W_self)[i];
        for (int i = tid; i < 8 * EE / 4; i += 256)
            ((float4*)&hb[0][0])[i] = ((const float4*)(h + n0 * EE))[i];
        __syncthreads();
        const int a = tid & 63, ng = tid >> 6;
        #pragma unroll
        for (int s = 0; s < 2; s++) {
            const int nl = ng + s * 4;
            float acc = 0.f;
            #pragma unroll
            for (int e = 0; e < EE; e++) acc = fmaf(hb[nl][e], Ws[e * EE + a], acc);
            g_self[(n0 + nl) * EE + a] = acc;
        }
    }

    grid_sync();

    // ================= PHASE 2: bucketed projections ==========================
    for (int u = bid; u < 2 * NREL * CHUNKS; u += NCTA) {
        const int binIdx = u >> 3, c0 = u & 7;
        const bool isK = binIdx >= NREL;
        const int  r   = isK ? binIdx - NREL : binIdx;
        const int  bin = (isK ? 256 : 0) + r;
        const int  cnt = g_cur[bin];
        const int  p   = c0 * PB;
        if (p >= cnt) continue;
        const int  np  = min(PB, cnt - p);
        const int* __restrict__ list = g_list + bin * CAP;
        float* Ws1 = smu.p.Ws1;
        float* Ws2 = smu.p.Ws2;
        float (*xb)[PB] = smu.p.xb;

        {
            const float4* w1 = (const float4*)((isK ? K : Q) + (size_t)r * EE * AA);
            #pragma unroll
            for (int i = tid; i < EE * AA / 4; i += 256) ((float4*)Ws1)[i] = w1[i];
            if (!isK) {
                const float4* w2 = (const float4*)(V + (size_t)r * EE * AA);
                #pragma unroll
                for (int i = tid; i < EE * AA / 4; i += 256) ((float4*)Ws2)[i] = w2[i];
            }
        }
        {
            const int tt = tid >> 2, qq = tid & 3;
            const bool valid = tt < np;
            int tok = valid ? list[p + tt] : 0;
            const int n = tok >> 5, m = tok & 31;
            const float* xp = (m == 0) ? (g_self + n * EE)
                                       : (msg + (size_t)(n * MMSG + m - 1) * EE);
            #pragma unroll
            for (int j = 0; j < 4; j++) {
                const int e = qq * 16 + j * 4;
                float4 xv = valid ? *(const float4*)(xp + e) : make_float4(0.f,0.f,0.f,0.f);
                xb[e + 0][tt] = xv.x; xb[e + 1][tt] = xv.y;
                xb[e + 2][tt] = xv.z; xb[e + 3][tt] = xv.w;
            }
        }
        __syncthreads();

        const int ag = tid & 15;
        const int tg = tid >> 4;
        if (!isK) {
            float a1[4][4], a2[4][4];
            #pragma unroll
            for (int j = 0; j < 4; j++)
                #pragma unroll
                for (int i = 0; i < 4; i++) { a1[j][i] = 0.f; a2[j][i] = 0.f; }
            #pragma unroll 8
            for (int e = 0; e < EE; e++) {
                const float4 w1 = *(const float4*)(Ws1 + e * AA + (ag << 2));
                const float4 w2 = *(const float4*)(Ws2 + e * AA + (ag << 2));
                const float4 xt = *(const float4*)(&xb[e][tg << 2]);
                const float xv[4]  = {xt.x, xt.y, xt.z, xt.w};
                const float w1v[4] = {w1.x, w1.y, w1.z, w1.w};
                const float w2v[4] = {w2.x, w2.y, w2.z, w2.w};
                #pragma unroll
                for (int j = 0; j < 4; j++)
                    #pragma unroll
                    for (int i = 0; i < 4; i++) {
                        a1[j][i] = fmaf(xv[j], w1v[i], a1[j][i]);
                        a2[j][i] = fmaf(xv[j], w2v[i], a2[j][i]);
                    }
            }
            #pragma unroll
            for (int j = 0; j < 4; j++) {
                const int ts = (tg << 2) + j;
                if (ts < np) {
                    const int tok = list[p + ts];
                    *(float4*)(g_q + (size_t)tok * AA + (ag << 2)) =
                        make_float4(a1[j][0], a1[j][1], a1[j][2], a1[j][3]);
                    *(float4*)(g_v + (size_t)tok * AA + (ag << 2)) =
                        make_float4(a2[j][0], a2[j][1], a2[j][2], a2[j][3]);
                }
            }
        } else {
            float a1[4][4];
            #pragma unroll
            for (int j = 0; j < 4; j++)
                #pragma unroll
                for (int i = 0; i < 4; i++) a1[j][i] = 0.f;
            #pragma unroll 8
            for (int e = 0; e < EE; e++) {
                const float4 w1 = *(const float4*)(Ws1 + e * AA + (ag << 2));
                const float4 xt = *(const float4*)(&xb[e][tg << 2]);
                const float xv[4]  = {xt.x, xt.y, xt.z, xt.w};
                const float w1v[4] = {w1.x, w1.y, w1.z, w1.w};
                #pragma unroll
                for (int j = 0; j < 4; j++)
                    #pragma unroll
                    for (int i = 0; i < 4; i++)
                        a1[j][i] = fmaf(xv[j], w1v[i], a1[j][i]);
            }
            #pragma unroll
            for (int j = 0; j < 4; j++) {
                const int ts = (tg << 2) + j;
                if (ts < np) {
                    const int tok = list[p + ts];
                    *(float4*)(g_k + (size_t)tok * AA + (ag << 2)) =
                        make_float4(a1[j][0], a1[j][1], a1[j][2], a1[j][3]);
                }
            }
        }
        __syncthreads();
    }

    grid_sync();

    // ================= PHASE 3: attention + pooling + FFN =====================
    if (bid == 0) { g_cur[tid] = 0; g_cur[256 + tid] = 0; }   // for next replay

    for (int u = bid; u < NN * 2; u += NCTA) {
        const int n = u >> 1, half = u & 1;
        AttnS& s = smu.a;

        const float4* gq = (const float4*)(g_q + (size_t)n * TT * AA);
        const float4* gk = (const float4*)(g_k + (size_t)n * TT * AA + (size_t)half * KHALF * AA);
        const float4* gv = (const float4*)(g_v + (size_t)n * TT * AA + (size_t)half * KHALF * AA);

        const int i1 = tid + 256;
        const float4 q0 = gq[tid], q1 = gq[i1];
        const float4 k0 = gk[tid];
        const float4 v0 = gv[tid];
        {
            const int r0 = tid >> 4, c0 = (tid & 15) << 2;
            const int r1 = i1 >> 4, c1 = (i1 & 15) << 2;
            *(float4*)(s.qs + r0 * QST + c0) = q0;
            *(float4*)(s.qs + r1 * QST + c1) = q1;
            *(float4*)(s.vs + r0 * QST + c0) = v0;
            s.kT[(c0 + 0) * KTST + r0] = k0.x;
            s.kT[(c0 + 1) * KTST + r0] = k0.y;
            s.kT[(c0 + 2) * KTST + r0] = k0.z;
            s.kT[(c0 + 3) * KTST + r0] = k0.w;
        }
        __syncthreads();

        {
            const int qr = tid >> 3, kc0 = (tid & 7) << 1;
            float a0 = 0.f, a1 = 0.f;
            #pragma unroll 16
            for (int e = 0; e < EE; e++) {
                const float qv = s.qs[qr * QST + e];
                const float2 k2 = *(const float2*)(s.kT + e * KTST + kc0);
                a0 = fmaf(qv, k2.x, a0);
                a1 = fmaf(qv, k2.y, a1);
            }
            s.sc[qr][kc0 + 0] = a0 * 0.125f;
            s.sc[qr][kc0 + 1] = a1 * 0.125f;
        }
        __syncthreads();

        if (tid < KHALF) {
            const int kc = tid;
            float mx = -1e30f;
            #pragma unroll
            for (int q = 0; q < TT; q++) mx = fmaxf(mx, s.sc[q][kc]);
            float sum = 0.f;
            #pragma unroll
            for (int q = 0; q < TT; q++) sum += __expf(s.sc[q][kc] - mx);
            s.att0[kc] = __expf(s.sc[0][kc] - mx) / sum;
        }
        __syncthreads();

        if (tid < AA) {
            float acc = 0.f;
            #pragma unroll
            for (int k = 0; k < KHALF; k++)
                acc = fmaf(s.att0[k], s.vs[k * QST + tid], acc);
            s.pooled[tid] = acc;
        }
        __syncthreads();

        if (tid < EE) {
            float acc = (half == 0) ? ffn_b[tid] : 0.f;
            #pragma unroll
            for (int a = 0; a < AA; a++)
                acc = fmaf(s.pooled[a], ffn_w[a * EE + tid], acc);
            atomicAdd(&out[n * EE + tid], acc);
        }
        __syncthreads();
    }
}

extern "C" void kernel_launch(void* const* d_in, const int* in_sizes, int n_in,
                              void* d_out, int out_size) {
    const float* h            = (const float*)d_in[0];
    const float* msg          = (const float*)d_in[1];
    const int*   msg_type     = (const int*)  d_in[2];
    const int*   r_label_node = (const int*)  d_in[3];
    const int*   r_label_msg  = (const int*)  d_in[4];
    const float* W_self       = (const float*)d_in[5];
    const float* Q            = (const float*)d_in[6];
    const float* K            = (const float*)d_in[7];
    const float* V            = (const float*)d_in[8];
    const float* ffn_w        = (const float*)d_in[9];
    const float* ffn_b        = (const float*)d_in[10];
    float* out = (float*)d_out;

    k_fused<<<NCTA, 256>>>(h, msg, msg_type, r_label_node, r_label_msg,
                           W_self, Q, K, V, ffn_w, ffn_b, out);
}

// round 15
// speedup vs baseline: 1.6166x; 1.6166x over previous
#include <cuda_runtime.h>
#include <cuda_bf16.h>

#define NN 512
#define TT 32
#define MMSG 31
#define EE 64
#define AA 64
#define NREL 201
#define NTOK (NN*TT)
#define PB 64
#define CAP 1024
#define CHUNKS 8
#define SELF_BIN (256 + 200)

// ---- packed f32x2 helpers (sm_103a) ------------------------------------------
__device__ __forceinline__ unsigned long long pack2(float x) {
    unsigned long long r;
    asm("mov.b64 %0, {%1, %1};" : "=l"(r) : "r"(__float_as_uint(x)));
    return r;
}
__device__ __forceinline__ unsigned long long fma2(unsigned long long a,
                                                   unsigned long long b,
                                                   unsigned long long c) {
    unsigned long long d;
    asm("fma.rn.f32x2 %0, %1, %2, %3;" : "=l"(d) : "l"(a), "l"(b), "l"(c));
    return d;
}
__device__ __forceinline__ float2 unpack2(unsigned long long v) {
    unsigned lo, hi;
    asm("mov.b64 {%0, %1}, %2;" : "=r"(lo), "=r"(hi) : "l"(v));
    return make_float2(__uint_as_float(lo), __uint_as_float(hi));
}

// ---- device scratch ---------------------------------------------------------
__device__ float g_self[NN * EE];
__device__ float g_q[NTOK * AA];
__device__ float g_k[NTOK * AA];
__device__ float g_v[NTOK * AA];
__device__ int   g_cur[2 * 256];       // zeroed at load; re-zeroed by k_attn
__device__ int   g_list[2 * 256 * CAP];

// ---- 1. prep (exact R11 proven version) ---------------------------------------
__global__ __launch_bounds__(256) void k_prep(const float* __restrict__ h,
                                              const float* __restrict__ W_self,
                                              const int* __restrict__ mt,
                                              const int* __restrict__ rln,
                                              const int* __restrict__ rlm,
                                              float* __restrict__ out) {
    const int b = blockIdx.x, tid = threadIdx.x;
    if (b < 64) {
        if (tid < 128)
            ((float4*)out)[b * 128 + tid] = make_float4(0.f, 0.f, 0.f, 0.f);
        const int t = b * 256 + tid;
        const int n = t >> 5, m = t & 31;
        if (m == 0) {
            const int rqv = rln[n];
            int p0 = atomicAdd(&g_cur[rqv], 1);
            g_list[rqv * CAP + p0] = t;
            g_list[SELF_BIN * CAP + n] = t;
        } else {
            const int i = n * MMSG + m - 1;
            const int rqv = rlm[i], rk = mt[i];
            int p0 = atomicAdd(&g_cur[rqv], 1);
            g_list[rqv * CAP + p0] = t;
            int p1 = atomicAdd(&g_cur[256 + rk], 1);
            g_list[(256 + rk) * CAP + p1] = t;
        }
        return;
    }
    if (b == 64 && tid == 0) g_cur[SELF_BIN] = NN;
    __shared__ float Ws[EE * EE];
    __shared__ float hb[8][EE];
    const int n0 = (b - 64) * 8;
    for (int i = tid; i < EE * EE / 4; i += 256)
        ((float4*)Ws)[i] = ((const float4*)W_self)[i];
    for (int i = tid; i < 8 * EE / 4; i += 256)
        ((float4*)&hb[0][0])[i] = ((const float4*)(h + n0 * EE))[i];
    __syncthreads();
    const int a = tid & 63, ng = tid >> 6;
    #pragma unroll
    for (int s = 0; s < 2; s++) {
        const int nl = ng + s * 4;
        float acc = 0.f;
        #pragma unroll
        for (int e = 0; e < EE; e++) acc = fmaf(hb[nl][e], Ws[e * EE + a], acc);
        g_self[(n0 + nl) * EE + a] = acc;
    }
}

// ---- 2. bucketed projections: f32x2-packed register tile ----------------------
__global__ __launch_bounds__(256) void k_proj(const float* __restrict__ msg,
                                              const float* __restrict__ Q,
                                              const float* __restrict__ K,
                                              const float* __restrict__ V) {
    const bool isK = blockIdx.x >= NREL;
    const int  r   = isK ? blockIdx.x - NREL : blockIdx.x;
    const int  bin = (isK ? 256 : 0) + r;
    const int  cnt = g_cur[bin];
    if ((int)blockIdx.y * PB >= cnt) return;

    __shared__ float Ws1[EE * AA];
    __shared__ float Ws2[EE * AA];
    __shared__ float xb[EE][PB];

    const int tid = threadIdx.x;
    const int* __restrict__ list = g_list + bin * CAP;

    {
        const float4* w1 = (const float4*)((isK ? K : Q) + (size_t)r * EE * AA);
        #pragma unroll
        for (int i = tid; i < EE * AA / 4; i += 256) ((float4*)Ws1)[i] = w1[i];
        if (!isK) {
            const float4* w2 = (const float4*)(V + (size_t)r * EE * AA);
            #pragma unroll
            for (int i = tid; i < EE * AA / 4; i += 256) ((float4*)Ws2)[i] = w2[i];
        }
    }

    const int ag = tid & 15;    // a-col group: cols ag*4..+3 (2 f32x2 pairs)
    const int tg = tid >> 4;    // token group: tokens tg*4..+3

    for (int c = blockIdx.y; c * PB < cnt; c += gridDim.y) {
        const int p  = c * PB;
        const int np = min(PB, cnt - p);
        __syncthreads();
        {
            const int tt = tid >> 2, qq = tid & 3;
            const bool valid = tt < np;
            int tok = valid ? list[p + tt] : 0;
            const int n = tok >> 5, m = tok & 31;
            const float* xp = (m == 0) ? (g_self + n * EE)
                                       : (msg + (size_t)(n * MMSG + m - 1) * EE);
            #pragma unroll
            for (int j = 0; j < 4; j++) {
                const int e = qq * 16 + j * 4;
                float4 xv = valid ? *(const float4*)(xp + e) : make_float4(0.f,0.f,0.f,0.f);
                xb[e + 0][tt] = xv.x; xb[e + 1][tt] = xv.y;
                xb[e + 2][tt] = xv.z; xb[e + 3][tt] = xv.w;
            }
        }
        __syncthreads();

        if (!isK) {
            unsigned long long a1[4][2], a2[4][2];
            #pragma unroll
            for (int j = 0; j < 4; j++)
                #pragma unroll
                for (int i = 0; i < 2; i++) { a1[j][i] = 0ull; a2[j][i] = 0ull; }
            #pragma unroll 8
            for (int e = 0; e < EE; e++) {
                const ulonglong2 w1p = *(const ulonglong2*)(Ws1 + e * AA + (ag << 2));
                const ulonglong2 w2p = *(const ulonglong2*)(Ws2 + e * AA + (ag << 2));
                const float4 xt = *(const float4*)(&xb[e][tg << 2]);
                const unsigned long long xd[4] = {pack2(xt.x), pack2(xt.y),
                                                  pack2(xt.z), pack2(xt.w)};
                #pragma unroll
                for (int j = 0; j < 4; j++) {
                    a1[j][0] = fma2(xd[j], w1p.x, a1[j][0]);
                    a1[j][1] = fma2(xd[j], w1p.y, a1[j][1]);
                    a2[j][0] = fma2(xd[j], w2p.x, a2[j][0]);
                    a2[j][1] = fma2(xd[j], w2p.y, a2[j][1]);
                }
            }
            #pragma unroll
            for (int j = 0; j < 4; j++) {
                const int ts = (tg << 2) + j;
                if (ts < np) {
                    const int tok = list[p + ts];
                    const float2 q01 = unpack2(a1[j][0]), q23 = unpack2(a1[j][1]);
                    const float2 v01 = unpack2(a2[j][0]), v23 = unpack2(a2[j][1]);
                    *(float4*)(g_q + (size_t)tok * AA + (ag << 2)) =
                        make_float4(q01.x, q01.y, q23.x, q23.y);
                    *(float4*)(g_v + (size_t)tok * AA + (ag << 2)) =
                        make_float4(v01.x, v01.y, v23.x, v23.y);
                }
            }
        } else {
            unsigned long long a1[4][2];
            #pragma unroll
            for (int j = 0; j < 4; j++) { a1[j][0] = 0ull; a1[j][1] = 0ull; }
            #pragma unroll 8
            for (int e = 0; e < EE; e++) {
                const ulonglong2 w1p = *(const ulonglong2*)(Ws1 + e * AA + (ag << 2));
                const float4 xt = *(const float4*)(&xb[e][tg << 2]);
                const unsigned long long xd[4] = {pack2(xt.x), pack2(xt.y),
                                                  pack2(xt.z), pack2(xt.w)};
                #pragma unroll
                for (int j = 0; j < 4; j++) {
                    a1[j][0] = fma2(xd[j], w1p.x, a1[j][0]);
                    a1[j][1] = fma2(xd[j], w1p.y, a1[j][1]);
                }
            }
            #pragma unroll
            for (int j = 0; j < 4; j++) {
                const int ts = (tg << 2) + j;
                if (ts < np) {
                    const int tok = list[p + ts];
                    const float2 k01 = unpack2(a1[j][0]), k23 = unpack2(a1[j][1]);
                    *(float4*)(g_k + (size_t)tok * AA + (ag << 2)) =
                        make_float4(k01.x, k01.y, k23.x, k23.y);
                }
            }
        }
    }
}

// ---- 3. attention (exact R11/R8 proven version) ---------------------------------
#define KHALF 16
#define QST 68
#define KTST 18
struct __align__(16) Attn2Smem {
    float qs[TT * QST];
    float vs[KHALF * QST];
    float kT[EE * KTST];
    float sc[TT][KHALF + 1];
    float att0[KHALF];
    float pooled[AA];
};
__global__ __launch_bounds__(256) void k_attn(const float* __restrict__ ffn_w,
                                              const float* __restrict__ ffn_b,
                                              float* __restrict__ out) {
    const int n = blockIdx.x, half = blockIdx.y, tid = threadIdx.x;
    if (n == 0 && half == 0) { g_cur[tid] = 0; g_cur[256 + tid] = 0; }
    __shared__ Attn2Smem s;

    const float4* gq = (const float4*)(g_q + (size_t)n * TT * AA);
    const float4* gk = (const float4*)(g_k + (size_t)n * TT * AA + (size_t)half * KHALF * AA);
    const float4* gv = (const float4*)(g_v + (size_t)n * TT * AA + (size_t)half * KHALF * AA);

    const int i1 = tid + 256;
    const float4 q0 = gq[tid], q1 = gq[i1];
    const float4 k0 = gk[tid];
    const float4 v0 = gv[tid];
    {
        const int r0 = tid >> 4, c0 = (tid & 15) << 2;
        const int r1 = i1 >> 4, c1 = (i1 & 15) << 2;
        *(float4*)(s.qs + r0 * QST + c0) = q0;
        *(float4*)(s.qs + r1 * QST + c1) = q1;
        *(float4*)(s.vs + r0 * QST + c0) = v0;
        s.kT[(c0 + 0) * KTST + r0] = k0.x;
        s.kT[(c0 + 1) * KTST + r0] = k0.y;
        s.kT[(c0 + 2) * KTST + r0] = k0.z;
        s.kT[(c0 + 3) * KTST + r0] = k0.w;
    }
    __syncthreads();

    {
        const int qr = tid >> 3, kc0 = (tid & 7) << 1;
        float a0 = 0.f, a1 = 0.f;
        #pragma unroll 16
        for (int e = 0; e < EE; e++) {
            const float qv = s.qs[qr * QST + e];
            const float2 k2 = *(const float2*)(s.kT + e * KTST + kc0);
            a0 = fmaf(qv, k2.x, a0);
            a1 = fmaf(qv, k2.y, a1);
        }
        s.sc[qr][kc0 + 0] = a0 * 0.125f;
        s.sc[qr][kc0 + 1] = a1 * 0.125f;
    }
    __syncthreads();

    if (tid < KHALF) {
        const int kc = tid;
        float mx = -1e30f;
        #pragma unroll
        for (int q = 0; q < TT; q++) mx = fmaxf(mx, s.sc[q][kc]);
        float sum = 0.f;
        #pragma unroll
        for (int q = 0; q < TT; q++) sum += __expf(s.sc[q][kc] - mx);
        s.att0[kc] = __expf(s.sc[0][kc] - mx) / sum;
    }
    __syncthreads();

    if (tid < AA) {
        float acc = 0.f;
        #pragma unroll
        for (int k = 0; k < KHALF; k++)
            acc = fmaf(s.att0[k], s.vs[k * QST + tid], acc);
        s.pooled[tid] = acc;
    }
    __syncthreads();

    if (tid < EE) {
        float acc = (half == 0) ? ffn_b[tid] : 0.f;
        #pragma unroll
        for (int a = 0; a < AA; a++)
            acc = fmaf(s.pooled[a], ffn_w[a * EE + tid], acc);
        atomicAdd(&out[n * EE + tid], acc);
    }
}

extern "C" void kernel_launch(void* const* d_in, const int* in_sizes, int n_in,
                              void* d_out, int out_size) {
    const float* h            = (const float*)d_in[0];
    const float* msg          = (const float*)d_in[1];
    const int*   msg_type     = (const int*)  d_in[2];
    const int*   r_label_node = (const int*)  d_in[3];
    const int*   r_label_msg  = (const int*)  d_in[4];
    const float* W_self       = (const float*)d_in[5];
    const float* Q            = (const float*)d_in[6];
    const float* K            = (const float*)d_in[7];
    const float* V            = (const float*)d_in[8];
    const float* ffn_w        = (const float*)d_in[9];
    const float* ffn_b        = (const float*)d_in[10];
    float* out = (float*)d_out;

    k_prep<<<128, 256>>>(h, W_self, msg_type, r_label_node, r_label_msg, out);
    dim3 pg(2 * NREL, CHUNKS);
    k_proj<<<pg, 256>>>(msg, Q, K, V);
    dim3 ag(NN, 2);
    k_attn<<<ag, 256>>>(ffn_w, ffn_b, out);
}